// round 13
// baseline (speedup 1.0000x reference)
#include <cuda_runtime.h>
#include <math.h>

// ---------------------------------------------------------------------------
// ChunkedDeltaNetLayer: B=2, S=1024, D_MODEL=1024, NHEAD=16, HEAD_DIM=64
//   q = l2norm(silu(x@Wq^T)), k = l2norm(silu(x@Wk^T)), v = silu(x@Wv^T)
//   beta = 2*sigmoid(x@Wb^T)
//   per (b,h): M(64x64); out_t = q^T M ; delta = v - M k ; M += beta k delta^T
//   y = RMSNorm(out)*rms_w ; result = y @ Wo^T
// All fp32.
// ---------------------------------------------------------------------------

#define BATCH 2
#define SEQ   1024
#define DM    1024
#define NH    16
#define HD    64
#define MROWS (BATCH*SEQ)   // 2048

// scratch (static device globals; no allocation allowed)
__device__ float g_q[MROWS*DM];
__device__ float g_k[MROWS*DM];
__device__ float g_v[MROWS*DM];
__device__ float g_beta[MROWS*NH];
__device__ float g_attn[MROWS*DM];
__device__ float g_normed[MROWS*DM];

__device__ __forceinline__ float silu_f(float a) {
    return a / (1.0f + expf(-a));
}

// ---------------------------------------------------------------------------
// Generic 64x64-tile NT GEMM body: C[m,n] = epilogue( sum_k A[m,k]*W[n,k] )
// A: (2048,1024) row-major, W: (1024,1024) row-major (rows = output features)
// 256 threads, 4x4 microtile. mode: 0 = plain, 1 = silu, 2 = silu + L2-norm
// over the 64 tile columns per row (tile == one head, N-tiles head-aligned).
// ---------------------------------------------------------------------------
__device__ __forceinline__ void gemm_tile(const float* __restrict__ A,
                                          const float* __restrict__ W,
                                          float* __restrict__ C,
                                          int m0, int n0, int mode)
{
    __shared__ float As[16][68];
    __shared__ float Bs[16][68];
    __shared__ float red[64][17];

    const int tid = threadIdx.x;            // 0..255
    const int row = tid >> 2;                // 0..63
    const int kq  = tid & 3;                 // 0..3
    const int tx  = tid & 15;                // 0..15 (n)
    const int ty  = tid >> 4;                // 0..15 (m)

    float acc[4][4];
#pragma unroll
    for (int i = 0; i < 4; i++)
#pragma unroll
        for (int j = 0; j < 4; j++) acc[i][j] = 0.0f;

    const float4* A4 = (const float4*)(A + (size_t)(m0 + row) * DM) + kq;
    const float4* B4 = (const float4*)(W + (size_t)(n0 + row) * DM) + kq;

    for (int k0 = 0; k0 < DM; k0 += 16) {
        float4 av = A4[k0 >> 2];
        float4 bv = B4[k0 >> 2];
        __syncthreads();
        As[kq*4+0][row] = av.x; As[kq*4+1][row] = av.y;
        As[kq*4+2][row] = av.z; As[kq*4+3][row] = av.w;
        Bs[kq*4+0][row] = bv.x; Bs[kq*4+1][row] = bv.y;
        Bs[kq*4+2][row] = bv.z; Bs[kq*4+3][row] = bv.w;
        __syncthreads();
#pragma unroll
        for (int kk = 0; kk < 16; ++kk) {
            float4 a = *(const float4*)&As[kk][ty << 2];
            float4 b = *(const float4*)&Bs[kk][tx << 2];
            float ar[4] = {a.x, a.y, a.z, a.w};
            float br[4] = {b.x, b.y, b.z, b.w};
#pragma unroll
            for (int i = 0; i < 4; i++)
#pragma unroll
                for (int j = 0; j < 4; j++) acc[i][j] += ar[i] * br[j];
        }
    }

    if (mode >= 1) {
#pragma unroll
        for (int i = 0; i < 4; i++)
#pragma unroll
            for (int j = 0; j < 4; j++) acc[i][j] = silu_f(acc[i][j]);
    }

    if (mode == 2) {
        __syncthreads();  // red overlaps usage; ensure prior loop done
#pragma unroll
        for (int i = 0; i < 4; i++) {
            float ss = acc[i][0]*acc[i][0] + acc[i][1]*acc[i][1]
                     + acc[i][2]*acc[i][2] + acc[i][3]*acc[i][3];
            red[(ty << 2) + i][tx] = ss;
        }
        __syncthreads();
        if (tid < 64) {
            float s = 0.0f;
#pragma unroll
            for (int c = 0; c < 16; ++c) s += red[tid][c];
            red[tid][16] = 1.0f / (sqrtf(s) + 1e-6f);
        }
        __syncthreads();
#pragma unroll
        for (int i = 0; i < 4; i++) {
            float inv = red[(ty << 2) + i][16];
#pragma unroll
            for (int j = 0; j < 4; j++) acc[i][j] *= inv;
        }
    }

#pragma unroll
    for (int i = 0; i < 4; i++) {
        float4 o = make_float4(acc[i][0], acc[i][1], acc[i][2], acc[i][3]);
        *(float4*)(C + (size_t)(m0 + (ty << 2) + i) * DM + n0 + (tx << 2)) = o;
    }
}

__global__ void __launch_bounds__(256)
k_gemm_qkv(const float* __restrict__ x, const float* __restrict__ Wq,
           const float* __restrict__ Wk, const float* __restrict__ Wv)
{
    int nt = blockIdx.x;              // 0..47
    int m0 = blockIdx.y << 6;
    const float* W;
    float* C;
    int mode;
    if (nt < 16)       { W = Wq; C = g_q; mode = 2; }
    else if (nt < 32)  { W = Wk; C = g_k; mode = 2; nt -= 16; }
    else               { W = Wv; C = g_v; mode = 1; nt -= 32; }
    gemm_tile(x, W, C, m0, nt << 6, mode);
}

__global__ void __launch_bounds__(256)
k_gemm_out(const float* __restrict__ Wo, float* __restrict__ out)
{
    gemm_tile(g_normed, Wo, out, blockIdx.y << 6, blockIdx.x << 6, 0);
}

// ---------------------------------------------------------------------------
// beta = 2*sigmoid(x @ Wb^T)  -- grid 2048 rows, 128 thr (16 heads x 8 lanes)
// ---------------------------------------------------------------------------
__global__ void __launch_bounds__(128)
k_beta(const float* __restrict__ x, const float* __restrict__ Wb)
{
    int m = blockIdx.x;
    int t = threadIdx.x;
    int h = t >> 3, g = t & 7;
    const float4* x4 = (const float4*)(x + (size_t)m * DM);
    const float4* w4 = (const float4*)(Wb + (size_t)h * DM);
    float a0 = 0.f, a1 = 0.f, a2 = 0.f, a3 = 0.f;
#pragma unroll 8
    for (int c = g; c < DM / 4; c += 8) {
        float4 xv = x4[c], wv = w4[c];
        a0 += xv.x * wv.x; a1 += xv.y * wv.y;
        a2 += xv.z * wv.z; a3 += xv.w * wv.w;
    }
    float a = (a0 + a1) + (a2 + a3);
    a += __shfl_xor_sync(0xffffffffu, a, 1);
    a += __shfl_xor_sync(0xffffffffu, a, 2);
    a += __shfl_xor_sync(0xffffffffu, a, 4);
    if (g == 0) g_beta[m * NH + h] = 2.0f / (1.0f + expf(-a));
}

// ---------------------------------------------------------------------------
// Sequential delta-rule scan. One block per (b,h) chain: 32 blocks, 128 thr.
// Thread t: idx = t>>1 (0..63), p = t&1 (half selector).
//   Mcol[i] = M[32p+i][idx]   (column slice, for out = q^T M)
//   Mrow[j] = M[idx][32p+j]   (row slice,    for r = M k)
// Both copies updated identically each step -> all matvecs are local dots.
// ---------------------------------------------------------------------------
__global__ void __launch_bounds__(128)
k_scan()
{
    const int b = blockIdx.x >> 4;
    const int h = blockIdx.x & 15;
    const int t = threadIdx.x;
    const int idx = t >> 1;
    const int p = t & 1;

    float Mcol[32], Mrow[32];
#pragma unroll
    for (int i = 0; i < 32; i++) { Mcol[i] = 0.f; Mrow[i] = 0.f; }

    __shared__ float qs[2][64], ks[2][64], ds[2][64];

    const int base = ((b * SEQ) * NH + h) * HD;  // offset at tt=0 for dim idx
    const float* __restrict__ qp = g_q + base + idx;
    const float* __restrict__ kp = g_k + base + idx;
    const float* __restrict__ vp = g_v + base + idx;
    const float* __restrict__ bp = g_beta + (b * SEQ) * NH + h;
    float* __restrict__ op = g_attn + base + idx;

    float qn = qp[0], kn = kp[0], vn = vp[0], bn = bp[0];

    for (int tt = 0; tt < SEQ; ++tt) {
        const int buf = tt & 1;
        const float qc = qn, kc = kn, vc = vn, bc = bn;
        if (p == 0) { qs[buf][idx] = qc; ks[buf][idx] = kc; }
        __syncthreads();

        // prefetch next timestep (hides L2/DRAM latency behind compute)
        if (tt < SEQ - 1) {
            qn = qp[(tt + 1) * DM];
            kn = kp[(tt + 1) * DM];
            vn = vp[(tt + 1) * DM];
            bn = bp[(tt + 1) * NH];
        }

        const float4* q4 = (const float4*)&qs[buf][p << 5];
        const float4* k4 = (const float4*)&ks[buf][p << 5];

        float o0 = 0.f, o1 = 0.f, o2 = 0.f, o3 = 0.f;
        float r0 = 0.f, r1 = 0.f, r2 = 0.f, r3 = 0.f;
#pragma unroll
        for (int c = 0; c < 8; ++c) {
            float4 qv = q4[c];
            float4 kv = k4[c];
            o0 += qv.x * Mcol[4*c+0]; o1 += qv.y * Mcol[4*c+1];
            o2 += qv.z * Mcol[4*c+2]; o3 += qv.w * Mcol[4*c+3];
            r0 += kv.x * Mrow[4*c+0]; r1 += kv.y * Mrow[4*c+1];
            r2 += kv.z * Mrow[4*c+2]; r3 += kv.w * Mrow[4*c+3];
        }
        float o = (o0 + o1) + (o2 + o3);
        float r = (r0 + r1) + (r2 + r3);
        o += __shfl_xor_sync(0xffffffffu, o, 1);
        r += __shfl_xor_sync(0xffffffffu, r, 1);

        const float delta = vc - r;
        if (p == 0) {
            ds[buf][idx] = delta;
            op[tt * DM] = o;          // strictly-causal read already done
        }
        __syncthreads();

        const float bk = bc * kc;     // beta * k[idx]    -> Mrow update
        const float bd = bc * delta;  // beta * delta[idx]-> Mcol update
        const float4* d4 = (const float4*)&ds[buf][p << 5];
#pragma unroll
        for (int c = 0; c < 8; ++c) {
            float4 dv = d4[c];
            float4 kv = k4[c];
            Mrow[4*c+0] += bk * dv.x; Mrow[4*c+1] += bk * dv.y;
            Mrow[4*c+2] += bk * dv.z; Mrow[4*c+3] += bk * dv.w;
            Mcol[4*c+0] += bd * kv.x; Mcol[4*c+1] += bd * kv.y;
            Mcol[4*c+2] += bd * kv.z; Mcol[4*c+3] += bd * kv.w;
        }
    }
}

// ---------------------------------------------------------------------------
// RMSNorm: y[m,k] = attn[m,k] / sqrt(mean(attn[m,:]^2)+1e-6) * rms_w[k]
// grid 2048, 256 threads (one float4 per thread)
// ---------------------------------------------------------------------------
__global__ void __launch_bounds__(256)
k_rms(const float* __restrict__ rms_w)
{
    const int m = blockIdx.x;
    const int t = threadIdx.x;
    const float4* a4 = (const float4*)(g_attn + (size_t)m * DM);
    float4 xv = a4[t];
    float ss = xv.x*xv.x + xv.y*xv.y + xv.z*xv.z + xv.w*xv.w;
#pragma unroll
    for (int o = 16; o; o >>= 1) ss += __shfl_xor_sync(0xffffffffu, ss, o);

    __shared__ float red[8];
    __shared__ float invs;
    if ((t & 31) == 0) red[t >> 5] = ss;
    __syncthreads();
    if (t == 0) {
        float s = 0.f;
#pragma unroll
        for (int i = 0; i < 8; i++) s += red[i];
        invs = 1.0f / sqrtf(s * (1.0f / (float)DM) + 1e-6f);
    }
    __syncthreads();
    float inv = invs;
    float4 wv = ((const float4*)rms_w)[t];
    float4 y = make_float4(xv.x * inv * wv.x, xv.y * inv * wv.y,
                           xv.z * inv * wv.z, xv.w * inv * wv.w);
    ((float4*)(g_normed + (size_t)m * DM))[t] = y;
}

// ---------------------------------------------------------------------------
extern "C" void kernel_launch(void* const* d_in, const int* in_sizes, int n_in,
                              void* d_out, int out_size)
{
    const float* x     = (const float*)d_in[0];
    const float* Wq    = (const float*)d_in[1];
    const float* Wk    = (const float*)d_in[2];
    const float* Wv    = (const float*)d_in[3];
    const float* Wb    = (const float*)d_in[4];
    const float* Wo    = (const float*)d_in[5];
    const float* rms_w = (const float*)d_in[6];
    float* out = (float*)d_out;

    k_gemm_qkv<<<dim3(48, 32), 256>>>(x, Wq, Wk, Wv);
    k_beta<<<2048, 128>>>(x, Wb);
    k_scan<<<32, 128>>>();
    k_rms<<<2048, 256>>>(rms_w);
    k_gemm_out<<<dim3(16, 32), 256>>>(Wo, out);
}

// round 14
// speedup vs baseline: 1.0024x; 1.0024x over previous
#include <cuda_runtime.h>
#include <math.h>

// ---------------------------------------------------------------------------
// ChunkedDeltaNetLayer: B=2, S=1024, D_MODEL=1024, NHEAD=16, HEAD_DIM=64
//   q = l2norm(silu(x@Wq^T)), k = l2norm(silu(x@Wk^T)), v = silu(x@Wv^T)
//   beta = 2*sigmoid(x@Wb^T)
//   per (b,h): M(64x64); out_t = q^T M ; delta = v - M k ; M += beta k delta^T
//   y = RMSNorm(out)*rms_w ; result = y @ Wo^T
// All fp32.
// ---------------------------------------------------------------------------

#define BATCH 2
#define SEQ   1024
#define DM    1024
#define NH    16
#define HD    64
#define MROWS (BATCH*SEQ)   // 2048

// scratch (static device globals; no allocation allowed)
__device__ float g_q[MROWS*DM];
__device__ float g_k[MROWS*DM];
__device__ float g_v[MROWS*DM];
__device__ float g_beta[MROWS*NH];
__device__ float g_attn[MROWS*DM];
__device__ float g_normed[MROWS*DM];

__device__ __forceinline__ float silu_f(float a) {
    return a / (1.0f + expf(-a));
}

// ---------------------------------------------------------------------------
// Generic 64x64-tile NT GEMM body: C[m,n] = epilogue( sum_k A[m,k]*W[n,k] )
// A: (2048,1024) row-major, W: (1024,1024) row-major (rows = output features)
// 256 threads, 4x4 microtile. mode: 0 = plain, 1 = silu, 2 = silu + L2-norm
// over the 64 tile columns per row (tile == one head, N-tiles head-aligned).
// ---------------------------------------------------------------------------
__device__ __forceinline__ void gemm_tile(const float* __restrict__ A,
                                          const float* __restrict__ W,
                                          float* __restrict__ C,
                                          int m0, int n0, int mode)
{
    __shared__ float As[16][68];
    __shared__ float Bs[16][68];
    __shared__ float red[64][17];

    const int tid = threadIdx.x;            // 0..255
    const int row = tid >> 2;                // 0..63
    const int kq  = tid & 3;                 // 0..3
    const int tx  = tid & 15;                // 0..15 (n)
    const int ty  = tid >> 4;                // 0..15 (m)

    float acc[4][4];
#pragma unroll
    for (int i = 0; i < 4; i++)
#pragma unroll
        for (int j = 0; j < 4; j++) acc[i][j] = 0.0f;

    const float4* A4 = (const float4*)(A + (size_t)(m0 + row) * DM) + kq;
    const float4* B4 = (const float4*)(W + (size_t)(n0 + row) * DM) + kq;

    for (int k0 = 0; k0 < DM; k0 += 16) {
        float4 av = A4[k0 >> 2];
        float4 bv = B4[k0 >> 2];
        __syncthreads();
        As[kq*4+0][row] = av.x; As[kq*4+1][row] = av.y;
        As[kq*4+2][row] = av.z; As[kq*4+3][row] = av.w;
        Bs[kq*4+0][row] = bv.x; Bs[kq*4+1][row] = bv.y;
        Bs[kq*4+2][row] = bv.z; Bs[kq*4+3][row] = bv.w;
        __syncthreads();
#pragma unroll
        for (int kk = 0; kk < 16; ++kk) {
            float4 a = *(const float4*)&As[kk][ty << 2];
            float4 b = *(const float4*)&Bs[kk][tx << 2];
            float ar[4] = {a.x, a.y, a.z, a.w};
            float br[4] = {b.x, b.y, b.z, b.w};
#pragma unroll
            for (int i = 0; i < 4; i++)
#pragma unroll
                for (int j = 0; j < 4; j++) acc[i][j] += ar[i] * br[j];
        }
    }

    if (mode >= 1) {
#pragma unroll
        for (int i = 0; i < 4; i++)
#pragma unroll
            for (int j = 0; j < 4; j++) acc[i][j] = silu_f(acc[i][j]);
    }

    if (mode == 2) {
        __syncthreads();  // red overlaps usage; ensure prior loop done
#pragma unroll
        for (int i = 0; i < 4; i++) {
            float ss = acc[i][0]*acc[i][0] + acc[i][1]*acc[i][1]
                     + acc[i][2]*acc[i][2] + acc[i][3]*acc[i][3];
            red[(ty << 2) + i][tx] = ss;
        }
        __syncthreads();
        if (tid < 64) {
            float s = 0.0f;
#pragma unroll
            for (int c = 0; c < 16; ++c) s += red[tid][c];
            red[tid][16] = 1.0f / (sqrtf(s) + 1e-6f);
        }
        __syncthreads();
#pragma unroll
        for (int i = 0; i < 4; i++) {
            float inv = red[(ty << 2) + i][16];
#pragma unroll
            for (int j = 0; j < 4; j++) acc[i][j] *= inv;
        }
    }

#pragma unroll
    for (int i = 0; i < 4; i++) {
        float4 o = make_float4(acc[i][0], acc[i][1], acc[i][2], acc[i][3]);
        *(float4*)(C + (size_t)(m0 + (ty << 2) + i) * DM + n0 + (tx << 2)) = o;
    }
}

__global__ void __launch_bounds__(256)
k_gemm_qkv(const float* __restrict__ x, const float* __restrict__ Wq,
           const float* __restrict__ Wk, const float* __restrict__ Wv)
{
    int nt = blockIdx.x;              // 0..47
    int m0 = blockIdx.y << 6;
    const float* W;
    float* C;
    int mode;
    if (nt < 16)       { W = Wq; C = g_q; mode = 2; }
    else if (nt < 32)  { W = Wk; C = g_k; mode = 2; nt -= 16; }
    else               { W = Wv; C = g_v; mode = 1; nt -= 32; }
    gemm_tile(x, W, C, m0, nt << 6, mode);
}

__global__ void __launch_bounds__(256)
k_gemm_out(const float* __restrict__ Wo, float* __restrict__ out)
{
    gemm_tile(g_normed, Wo, out, blockIdx.y << 6, blockIdx.x << 6, 0);
}

// ---------------------------------------------------------------------------
// beta = 2*sigmoid(x @ Wb^T)  -- grid 2048 rows, 128 thr (16 heads x 8 lanes)
// ---------------------------------------------------------------------------
__global__ void __launch_bounds__(128)
k_beta(const float* __restrict__ x, const float* __restrict__ Wb)
{
    int m = blockIdx.x;
    int t = threadIdx.x;
    int h = t >> 3, g = t & 7;
    const float4* x4 = (const float4*)(x + (size_t)m * DM);
    const float4* w4 = (const float4*)(Wb + (size_t)h * DM);
    float a0 = 0.f, a1 = 0.f, a2 = 0.f, a3 = 0.f;
#pragma unroll 8
    for (int c = g; c < DM / 4; c += 8) {
        float4 xv = x4[c], wv = w4[c];
        a0 += xv.x * wv.x; a1 += xv.y * wv.y;
        a2 += xv.z * wv.z; a3 += xv.w * wv.w;
    }
    float a = (a0 + a1) + (a2 + a3);
    a += __shfl_xor_sync(0xffffffffu, a, 1);
    a += __shfl_xor_sync(0xffffffffu, a, 2);
    a += __shfl_xor_sync(0xffffffffu, a, 4);
    if (g == 0) g_beta[m * NH + h] = 2.0f / (1.0f + expf(-a));
}

// ---------------------------------------------------------------------------
// Sequential delta-rule scan. One block per (b,h) chain: 32 blocks, 128 thr.
// Thread t: idx = t>>1 (0..63), p = t&1 (half selector).
//   Mcol[i] = M[32p+i][idx]   (column slice, for out = q^T M)
//   Mrow[j] = M[idx][32p+j]   (row slice,    for r = M k)
// Both copies updated identically each step -> all matvecs are local dots.
// ---------------------------------------------------------------------------
__global__ void __launch_bounds__(128)
k_scan()
{
    const int b = blockIdx.x >> 4;
    const int h = blockIdx.x & 15;
    const int t = threadIdx.x;
    const int idx = t >> 1;
    const int p = t & 1;

    float Mcol[32], Mrow[32];
#pragma unroll
    for (int i = 0; i < 32; i++) { Mcol[i] = 0.f; Mrow[i] = 0.f; }

    __shared__ float qs[2][64], ks[2][64], ds[2][64];

    const int base = ((b * SEQ) * NH + h) * HD;  // offset at tt=0 for dim idx
    const float* __restrict__ qp = g_q + base + idx;
    const float* __restrict__ kp = g_k + base + idx;
    const float* __restrict__ vp = g_v + base + idx;
    const float* __restrict__ bp = g_beta + (b * SEQ) * NH + h;
    float* __restrict__ op = g_attn + base + idx;

    float qn = qp[0], kn = kp[0], vn = vp[0], bn = bp[0];

    for (int tt = 0; tt < SEQ; ++tt) {
        const int buf = tt & 1;
        const float qc = qn, kc = kn, vc = vn, bc = bn;
        if (p == 0) { qs[buf][idx] = qc; ks[buf][idx] = kc; }
        __syncthreads();

        // prefetch next timestep (hides L2/DRAM latency behind compute)
        if (tt < SEQ - 1) {
            qn = qp[(tt + 1) * DM];
            kn = kp[(tt + 1) * DM];
            vn = vp[(tt + 1) * DM];
            bn = bp[(tt + 1) * NH];
        }

        const float4* q4 = (const float4*)&qs[buf][p << 5];
        const float4* k4 = (const float4*)&ks[buf][p << 5];

        float o0 = 0.f, o1 = 0.f, o2 = 0.f, o3 = 0.f;
        float r0 = 0.f, r1 = 0.f, r2 = 0.f, r3 = 0.f;
#pragma unroll
        for (int c = 0; c < 8; ++c) {
            float4 qv = q4[c];
            float4 kv = k4[c];
            o0 += qv.x * Mcol[4*c+0]; o1 += qv.y * Mcol[4*c+1];
            o2 += qv.z * Mcol[4*c+2]; o3 += qv.w * Mcol[4*c+3];
            r0 += kv.x * Mrow[4*c+0]; r1 += kv.y * Mrow[4*c+1];
            r2 += kv.z * Mrow[4*c+2]; r3 += kv.w * Mrow[4*c+3];
        }
        float o = (o0 + o1) + (o2 + o3);
        float r = (r0 + r1) + (r2 + r3);
        o += __shfl_xor_sync(0xffffffffu, o, 1);
        r += __shfl_xor_sync(0xffffffffu, r, 1);

        const float delta = vc - r;
        if (p == 0) {
            ds[buf][idx] = delta;
            op[tt * DM] = o;          // strictly-causal read already done
        }
        __syncthreads();

        const float bk = bc * kc;     // beta * k[idx]    -> Mrow update
        const float bd = bc * delta;  // beta * delta[idx]-> Mcol update
        const float4* d4 = (const float4*)&ds[buf][p << 5];
#pragma unroll
        for (int c = 0; c < 8; ++c) {
            float4 dv = d4[c];
            float4 kv = k4[c];
            Mrow[4*c+0] += bk * dv.x; Mrow[4*c+1] += bk * dv.y;
            Mrow[4*c+2] += bk * dv.z; Mrow[4*c+3] += bk * dv.w;
            Mcol[4*c+0] += bd * kv.x; Mcol[4*c+1] += bd * kv.y;
            Mcol[4*c+2] += bd * kv.z; Mcol[4*c+3] += bd * kv.w;
        }
    }
}

// ---------------------------------------------------------------------------
// RMSNorm: y[m,k] = attn[m,k] / sqrt(mean(attn[m,:]^2)+1e-6) * rms_w[k]
// grid 2048, 256 threads (one float4 per thread)
// ---------------------------------------------------------------------------
__global__ void __launch_bounds__(256)
k_rms(const float* __restrict__ rms_w)
{
    const int m = blockIdx.x;
    const int t = threadIdx.x;
    const float4* a4 = (const float4*)(g_attn + (size_t)m * DM);
    float4 xv = a4[t];
    float ss = xv.x*xv.x + xv.y*xv.y + xv.z*xv.z + xv.w*xv.w;
#pragma unroll
    for (int o = 16; o; o >>= 1) ss += __shfl_xor_sync(0xffffffffu, ss, o);

    __shared__ float red[8];
    __shared__ float invs;
    if ((t & 31) == 0) red[t >> 5] = ss;
    __syncthreads();
    if (t == 0) {
        float s = 0.f;
#pragma unroll
        for (int i = 0; i < 8; i++) s += red[i];
        invs = 1.0f / sqrtf(s * (1.0f / (float)DM) + 1e-6f);
    }
    __syncthreads();
    float inv = invs;
    float4 wv = ((const float4*)rms_w)[t];
    float4 y = make_float4(xv.x * inv * wv.x, xv.y * inv * wv.y,
                           xv.z * inv * wv.z, xv.w * inv * wv.w);
    ((float4*)(g_normed + (size_t)m * DM))[t] = y;
}

// ---------------------------------------------------------------------------
extern "C" void kernel_launch(void* const* d_in, const int* in_sizes, int n_in,
                              void* d_out, int out_size)
{
    const float* x     = (const float*)d_in[0];
    const float* Wq    = (const float*)d_in[1];
    const float* Wk    = (const float*)d_in[2];
    const float* Wv    = (const float*)d_in[3];
    const float* Wb    = (const float*)d_in[4];
    const float* Wo    = (const float*)d_in[5];
    const float* rms_w = (const float*)d_in[6];
    float* out = (float*)d_out;

    k_gemm_qkv<<<dim3(48, 32), 256>>>(x, Wq, Wk, Wv);
    k_beta<<<2048, 128>>>(x, Wb);
    k_scan<<<32, 128>>>();
    k_rms<<<2048, 256>>>(rms_w);
    k_gemm_out<<<dim3(16, 32), 256>>>(Wo, out);
}

// round 15
// speedup vs baseline: 1.0027x; 1.0004x over previous
#include <cuda_runtime.h>
#include <math.h>

// ---------------------------------------------------------------------------
// ChunkedDeltaNetLayer: B=2, S=1024, D_MODEL=1024, NHEAD=16, HEAD_DIM=64
//   q = l2norm(silu(x@Wq^T)), k = l2norm(silu(x@Wk^T)), v = silu(x@Wv^T)
//   beta = 2*sigmoid(x@Wb^T)
//   per (b,h): M(64x64); out_t = q^T M ; delta = v - M k ; M += beta k delta^T
//   y = RMSNorm(out)*rms_w ; result = y @ Wo^T
// All fp32.
// ---------------------------------------------------------------------------

#define BATCH 2
#define SEQ   1024
#define DM    1024
#define NH    16
#define HD    64
#define MROWS (BATCH*SEQ)   // 2048

// scratch (static device globals; no allocation allowed)
__device__ float g_q[MROWS*DM];
__device__ float g_k[MROWS*DM];
__device__ float g_v[MROWS*DM];
__device__ float g_beta[MROWS*NH];
__device__ float g_attn[MROWS*DM];
__device__ float g_normed[MROWS*DM];

__device__ __forceinline__ float silu_f(float a) {
    return a / (1.0f + expf(-a));
}

// ---------------------------------------------------------------------------
// Generic 64x64-tile NT GEMM body: C[m,n] = epilogue( sum_k A[m,k]*W[n,k] )
// A: (2048,1024) row-major, W: (1024,1024) row-major (rows = output features)
// 256 threads, 4x4 microtile. mode: 0 = plain, 1 = silu, 2 = silu + L2-norm
// over the 64 tile columns per row (tile == one head, N-tiles head-aligned).
// ---------------------------------------------------------------------------
__device__ __forceinline__ void gemm_tile(const float* __restrict__ A,
                                          const float* __restrict__ W,
                                          float* __restrict__ C,
                                          int m0, int n0, int mode)
{
    __shared__ float As[16][68];
    __shared__ float Bs[16][68];
    __shared__ float red[64][17];

    const int tid = threadIdx.x;            // 0..255
    const int row = tid >> 2;                // 0..63
    const int kq  = tid & 3;                 // 0..3
    const int tx  = tid & 15;                // 0..15 (n)
    const int ty  = tid >> 4;                // 0..15 (m)

    float acc[4][4];
#pragma unroll
    for (int i = 0; i < 4; i++)
#pragma unroll
        for (int j = 0; j < 4; j++) acc[i][j] = 0.0f;

    const float4* A4 = (const float4*)(A + (size_t)(m0 + row) * DM) + kq;
    const float4* B4 = (const float4*)(W + (size_t)(n0 + row) * DM) + kq;

    for (int k0 = 0; k0 < DM; k0 += 16) {
        float4 av = A4[k0 >> 2];
        float4 bv = B4[k0 >> 2];
        __syncthreads();
        As[kq*4+0][row] = av.x; As[kq*4+1][row] = av.y;
        As[kq*4+2][row] = av.z; As[kq*4+3][row] = av.w;
        Bs[kq*4+0][row] = bv.x; Bs[kq*4+1][row] = bv.y;
        Bs[kq*4+2][row] = bv.z; Bs[kq*4+3][row] = bv.w;
        __syncthreads();
#pragma unroll
        for (int kk = 0; kk < 16; ++kk) {
            float4 a = *(const float4*)&As[kk][ty << 2];
            float4 b = *(const float4*)&Bs[kk][tx << 2];
            float ar[4] = {a.x, a.y, a.z, a.w};
            float br[4] = {b.x, b.y, b.z, b.w};
#pragma unroll
            for (int i = 0; i < 4; i++)
#pragma unroll
                for (int j = 0; j < 4; j++) acc[i][j] += ar[i] * br[j];
        }
    }

    if (mode >= 1) {
#pragma unroll
        for (int i = 0; i < 4; i++)
#pragma unroll
            for (int j = 0; j < 4; j++) acc[i][j] = silu_f(acc[i][j]);
    }

    if (mode == 2) {
        __syncthreads();  // red overlaps usage; ensure prior loop done
#pragma unroll
        for (int i = 0; i < 4; i++) {
            float ss = acc[i][0]*acc[i][0] + acc[i][1]*acc[i][1]
                     + acc[i][2]*acc[i][2] + acc[i][3]*acc[i][3];
            red[(ty << 2) + i][tx] = ss;
        }
        __syncthreads();
        if (tid < 64) {
            float s = 0.0f;
#pragma unroll
            for (int c = 0; c < 16; ++c) s += red[tid][c];
            red[tid][16] = 1.0f / (sqrtf(s) + 1e-6f);
        }
        __syncthreads();
#pragma unroll
        for (int i = 0; i < 4; i++) {
            float inv = red[(ty << 2) + i][16];
#pragma unroll
            for (int j = 0; j < 4; j++) acc[i][j] *= inv;
        }
    }

#pragma unroll
    for (int i = 0; i < 4; i++) {
        float4 o = make_float4(acc[i][0], acc[i][1], acc[i][2], acc[i][3]);
        *(float4*)(C + (size_t)(m0 + (ty << 2) + i) * DM + n0 + (tx << 2)) = o;
    }
}

__global__ void __launch_bounds__(256)
k_gemm_qkv(const float* __restrict__ x, const float* __restrict__ Wq,
           const float* __restrict__ Wk, const float* __restrict__ Wv)
{
    int nt = blockIdx.x;              // 0..47
    int m0 = blockIdx.y << 6;
    const float* W;
    float* C;
    int mode;
    if (nt < 16)       { W = Wq; C = g_q; mode = 2; }
    else if (nt < 32)  { W = Wk; C = g_k; mode = 2; nt -= 16; }
    else               { W = Wv; C = g_v; mode = 1; nt -= 32; }
    gemm_tile(x, W, C, m0, nt << 6, mode);
}

__global__ void __launch_bounds__(256)
k_gemm_out(const float* __restrict__ Wo, float* __restrict__ out)
{
    gemm_tile(g_normed, Wo, out, blockIdx.y << 6, blockIdx.x << 6, 0);
}

// ---------------------------------------------------------------------------
// beta = 2*sigmoid(x @ Wb^T)  -- grid 2048 rows, 128 thr (16 heads x 8 lanes)
// ---------------------------------------------------------------------------
__global__ void __launch_bounds__(128)
k_beta(const float* __restrict__ x, const float* __restrict__ Wb)
{
    int m = blockIdx.x;
    int t = threadIdx.x;
    int h = t >> 3, g = t & 7;
    const float4* x4 = (const float4*)(x + (size_t)m * DM);
    const float4* w4 = (const float4*)(Wb + (size_t)h * DM);
    float a0 = 0.f, a1 = 0.f, a2 = 0.f, a3 = 0.f;
#pragma unroll 8
    for (int c = g; c < DM / 4; c += 8) {
        float4 xv = x4[c], wv = w4[c];
        a0 += xv.x * wv.x; a1 += xv.y * wv.y;
        a2 += xv.z * wv.z; a3 += xv.w * wv.w;
    }
    float a = (a0 + a1) + (a2 + a3);
    a += __shfl_xor_sync(0xffffffffu, a, 1);
    a += __shfl_xor_sync(0xffffffffu, a, 2);
    a += __shfl_xor_sync(0xffffffffu, a, 4);
    if (g == 0) g_beta[m * NH + h] = 2.0f / (1.0f + expf(-a));
}

// ---------------------------------------------------------------------------
// Sequential delta-rule scan. One block per (b,h) chain: 32 blocks, 128 thr.
// Thread t: idx = t>>1 (0..63), p = t&1 (half selector).
//   Mcol[i] = M[32p+i][idx]   (column slice, for out = q^T M)
//   Mrow[j] = M[idx][32p+j]   (row slice,    for r = M k)
// Both copies updated identically each step -> all matvecs are local dots.
// ---------------------------------------------------------------------------
__global__ void __launch_bounds__(128)
k_scan()
{
    const int b = blockIdx.x >> 4;
    const int h = blockIdx.x & 15;
    const int t = threadIdx.x;
    const int idx = t >> 1;
    const int p = t & 1;

    float Mcol[32], Mrow[32];
#pragma unroll
    for (int i = 0; i < 32; i++) { Mcol[i] = 0.f; Mrow[i] = 0.f; }

    __shared__ float qs[2][64], ks[2][64], ds[2][64];

    const int base = ((b * SEQ) * NH + h) * HD;  // offset at tt=0 for dim idx
    const float* __restrict__ qp = g_q + base + idx;
    const float* __restrict__ kp = g_k + base + idx;
    const float* __restrict__ vp = g_v + base + idx;
    const float* __restrict__ bp = g_beta + (b * SEQ) * NH + h;
    float* __restrict__ op = g_attn + base + idx;

    float qn = qp[0], kn = kp[0], vn = vp[0], bn = bp[0];

    for (int tt = 0; tt < SEQ; ++tt) {
        const int buf = tt & 1;
        const float qc = qn, kc = kn, vc = vn, bc = bn;
        if (p == 0) { qs[buf][idx] = qc; ks[buf][idx] = kc; }
        __syncthreads();

        // prefetch next timestep (hides L2/DRAM latency behind compute)
        if (tt < SEQ - 1) {
            qn = qp[(tt + 1) * DM];
            kn = kp[(tt + 1) * DM];
            vn = vp[(tt + 1) * DM];
            bn = bp[(tt + 1) * NH];
        }

        const float4* q4 = (const float4*)&qs[buf][p << 5];
        const float4* k4 = (const float4*)&ks[buf][p << 5];

        float o0 = 0.f, o1 = 0.f, o2 = 0.f, o3 = 0.f;
        float r0 = 0.f, r1 = 0.f, r2 = 0.f, r3 = 0.f;
#pragma unroll
        for (int c = 0; c < 8; ++c) {
            float4 qv = q4[c];
            float4 kv = k4[c];
            o0 += qv.x * Mcol[4*c+0]; o1 += qv.y * Mcol[4*c+1];
            o2 += qv.z * Mcol[4*c+2]; o3 += qv.w * Mcol[4*c+3];
            r0 += kv.x * Mrow[4*c+0]; r1 += kv.y * Mrow[4*c+1];
            r2 += kv.z * Mrow[4*c+2]; r3 += kv.w * Mrow[4*c+3];
        }
        float o = (o0 + o1) + (o2 + o3);
        float r = (r0 + r1) + (r2 + r3);
        o += __shfl_xor_sync(0xffffffffu, o, 1);
        r += __shfl_xor_sync(0xffffffffu, r, 1);

        const float delta = vc - r;
        if (p == 0) {
            ds[buf][idx] = delta;
            op[tt * DM] = o;          // strictly-causal read already done
        }
        __syncthreads();

        const float bk = bc * kc;     // beta * k[idx]    -> Mrow update
        const float bd = bc * delta;  // beta * delta[idx]-> Mcol update
        const float4* d4 = (const float4*)&ds[buf][p << 5];
#pragma unroll
        for (int c = 0; c < 8; ++c) {
            float4 dv = d4[c];
            float4 kv = k4[c];
            Mrow[4*c+0] += bk * dv.x; Mrow[4*c+1] += bk * dv.y;
            Mrow[4*c+2] += bk * dv.z; Mrow[4*c+3] += bk * dv.w;
            Mcol[4*c+0] += bd * kv.x; Mcol[4*c+1] += bd * kv.y;
            Mcol[4*c+2] += bd * kv.z; Mcol[4*c+3] += bd * kv.w;
        }
    }
}

// ---------------------------------------------------------------------------
// RMSNorm: y[m,k] = attn[m,k] / sqrt(mean(attn[m,:]^2)+1e-6) * rms_w[k]
// grid 2048, 256 threads (one float4 per thread)
// ---------------------------------------------------------------------------
__global__ void __launch_bounds__(256)
k_rms(const float* __restrict__ rms_w)
{
    const int m = blockIdx.x;
    const int t = threadIdx.x;
    const float4* a4 = (const float4*)(g_attn + (size_t)m * DM);
    float4 xv = a4[t];
    float ss = xv.x*xv.x + xv.y*xv.y + xv.z*xv.z + xv.w*xv.w;
#pragma unroll
    for (int o = 16; o; o >>= 1) ss += __shfl_xor_sync(0xffffffffu, ss, o);

    __shared__ float red[8];
    __shared__ float invs;
    if ((t & 31) == 0) red[t >> 5] = ss;
    __syncthreads();
    if (t == 0) {
        float s = 0.f;
#pragma unroll
        for (int i = 0; i < 8; i++) s += red[i];
        invs = 1.0f / sqrtf(s * (1.0f / (float)DM) + 1e-6f);
    }
    __syncthreads();
    float inv = invs;
    float4 wv = ((const float4*)rms_w)[t];
    float4 y = make_float4(xv.x * inv * wv.x, xv.y * inv * wv.y,
                           xv.z * inv * wv.z, xv.w * inv * wv.w);
    ((float4*)(g_normed + (size_t)m * DM))[t] = y;
}

// ---------------------------------------------------------------------------
extern "C" void kernel_launch(void* const* d_in, const int* in_sizes, int n_in,
                              void* d_out, int out_size)
{
    const float* x     = (const float*)d_in[0];
    const float* Wq    = (const float*)d_in[1];
    const float* Wk    = (const float*)d_in[2];
    const float* Wv    = (const float*)d_in[3];
    const float* Wb    = (const float*)d_in[4];
    const float* Wo    = (const float*)d_in[5];
    const float* rms_w = (const float*)d_in[6];
    float* out = (float*)d_out;

    k_gemm_qkv<<<dim3(48, 32), 256>>>(x, Wq, Wk, Wv);
    k_beta<<<2048, 128>>>(x, Wb);
    k_scan<<<32, 128>>>();
    k_rms<<<2048, 256>>>(rms_w);
    k_gemm_out<<<dim3(16, 32), 256>>>(Wo, out);
}